// round 1
// baseline (speedup 1.0000x reference)
#include <cuda_runtime.h>

#define BB 512
#define SS 128
#define VV 2048
#define ROWS (BB*SS)

// Scratch (allocation-free: device globals)
__device__ float g_ce[ROWS];
__device__ int   g_pred[ROWS];
__device__ float g_part[BB * 6];

__device__ __forceinline__ float pick4(float4 q, int k) {
    return (k == 0) ? q.x : (k == 1) ? q.y : (k == 2) ? q.z : q.w;
}

// ---------------------------------------------------------------------------
// Kernel 1: one block per (b,s) row of 2048 logits.
// Computes label-smoothed CE (stable log-softmax) and argmax per row.
// ---------------------------------------------------------------------------
__global__ void __launch_bounds__(256) k_row(const float* __restrict__ logits,
                                             const int*   __restrict__ tgt)
{
    const int row = blockIdx.x;
    const int tid = threadIdx.x;
    const float4* base = reinterpret_cast<const float4*>(logits) + (size_t)row * (VV / 4);

    float4 a = base[tid];
    float4 b = base[tid + 256];
    float v[8] = {a.x, a.y, a.z, a.w, b.x, b.y, b.z, b.w};

    // local max (first-index tie-break), local sum
    float mx = v[0];
    int   mi = tid * 4;
    float sx = 0.f;
#pragma unroll
    for (int k = 0; k < 8; k++) {
        int gi = (k < 4) ? (tid * 4 + k) : ((tid + 256) * 4 + (k - 4));
        if (v[k] > mx) { mx = v[k]; mi = gi; }   // strict > keeps earliest index
        sx += v[k];
    }

    // pick logit at target index
    __shared__ float s_xt;
    const int t  = tgt[row];
    const int f4 = t >> 2;
    if (f4 == tid)             s_xt = pick4(a, t & 3);
    else if (f4 == tid + 256)  s_xt = pick4(b, t & 3);

    // warp reduce (max,idx) and sum
#pragma unroll
    for (int off = 16; off; off >>= 1) {
        float om = __shfl_down_sync(0xFFFFFFFFu, mx, off);
        int   oi = __shfl_down_sync(0xFFFFFFFFu, mi, off);
        if (om > mx || (om == mx && oi < mi)) { mx = om; mi = oi; }
        sx += __shfl_down_sync(0xFFFFFFFFu, sx, off);
    }

    __shared__ float s_mx[8];
    __shared__ int   s_mi[8];
    __shared__ float s_sx[8];
    const int wid = tid >> 5, lane = tid & 31;
    if (lane == 0) { s_mx[wid] = mx; s_mi[wid] = mi; s_sx[wid] = sx; }
    __syncthreads();

    __shared__ float bmx, bsx;
    __shared__ int   bmi;
    if (tid == 0) {
        float m = s_mx[0]; int i = s_mi[0]; float s = s_sx[0];
#pragma unroll
        for (int w = 1; w < 8; w++) {
            if (s_mx[w] > m || (s_mx[w] == m && s_mi[w] < i)) { m = s_mx[w]; i = s_mi[w]; }
            s += s_sx[w];
        }
        bmx = m; bmi = i; bsx = s;
    }
    __syncthreads();

    const float rm = bmx;
    float se = 0.f;
#pragma unroll
    for (int k = 0; k < 8; k++) se += __expf(v[k] - rm);

#pragma unroll
    for (int off = 16; off; off >>= 1)
        se += __shfl_down_sync(0xFFFFFFFFu, se, off);
    if (lane == 0) s_sx[wid] = se;   // safe: barrier above separates previous reads
    __syncthreads();

    if (tid == 0) {
        float tot = 0.f;
#pragma unroll
        for (int w = 0; w < 8; w++) tot += s_sx[w];
        const float lse = rm + logf(tot);
        float cev = 0.f;
        if (t != 0) {  // PAD == 0
            const float nll = lse - s_xt;
            const float smo = lse - bsx * (1.0f / (float)VV);
            cev = 0.9f * nll + 0.1f * smo;       // (1-LS)*nll + LS*(-mean logp)
        }
        g_ce[row]   = cev;
        g_pred[row] = bmi;
    }
}

// ---------------------------------------------------------------------------
// Kernel 2: one block per batch row (128 threads = S positions).
// Position weights, length penalty, analytic n-gram counts; per-batch partials.
// ---------------------------------------------------------------------------
__global__ void __launch_bounds__(128) k_batch(const int* __restrict__ tgt)
{
    const int b = blockIdx.x, j = threadIdx.x;
    __shared__ int s_t[SS];
    __shared__ int s_p[SS];

    const int t = tgt[b * SS + j];
    const int p = g_pred[b * SS + j];
    const float c = g_ce[b * SS + j];
    s_t[j] = t; s_p[j] = p;

    const int len  = __syncthreads_count(t != 0);
    const int plen = __syncthreads_count(p != 0);
    const int av   = __syncthreads_or((j < SS - 2) && (t != 0));

    // position weight: exact replication of the sequential jnp.where chain
    float bw = 1.0f;
    if (j < len) {
        const int L = len;
        float w = 1.0f + ((float)j / (float)L) * 0.5f;
        if (j == L - 1)            w = 4.5f;   // END_W * 1.5
        if (L >= 2 && j == L - 2)  w = 3.0f;   // END_W * 1.0
        if (L >= 3 && j == L - 3)  w = 2.4f;   // END_W * 0.8
        if (L >= 4 && j >= L / 3 && j < (2 * L) / 3) w *= 1.3f;
        if (L <= 4)                w *= 1.2f;
        bw = w;
    }
    const float cw = c * bw;

    float big = 0.f, tri = 0.f;
    if (j < SS - 1) {
        const bool pb = (s_p[j] == s_p[j + 1]);
        const bool tb = (s_t[j] == s_t[j + 1]);
        const bool mb = pb && tb && (s_p[j] == s_t[j]);
        const float wq = (j >= SS - 3) ? 2.25f : 1.0f;           // 1.5^2
        big = ((float)pb + (float)tb - 2.0f * (float)mb) * wq;
    }
    if (j < SS - 2) {
        const bool pb0 = (s_p[j] == s_p[j + 1]), pb1 = (s_p[j + 1] == s_p[j + 2]);
        const bool tb0 = (s_t[j] == s_t[j + 1]), tb1 = (s_t[j + 1] == s_t[j + 2]);
        const bool pt = pb0 && pb1, tt = tb0 && tb1;
        const bool mt = pt && tt && (s_p[j] == s_t[j]);
        const float wq = (j >= SS - 4) ? 4.0f : 1.0f;            // 2.0^2
        tri = ((float)pt + (float)tt - 2.0f * (float)mt) * wq;
    }

    // block reduce 4 floats (deterministic)
    float r0 = cw, r1 = bw, r2 = big, r3 = tri;
#pragma unroll
    for (int off = 16; off; off >>= 1) {
        r0 += __shfl_down_sync(0xFFFFFFFFu, r0, off);
        r1 += __shfl_down_sync(0xFFFFFFFFu, r1, off);
        r2 += __shfl_down_sync(0xFFFFFFFFu, r2, off);
        r3 += __shfl_down_sync(0xFFFFFFFFu, r3, off);
    }
    __shared__ float red[4][4];
    const int wid = j >> 5, lane = j & 31;
    if (lane == 0) { red[wid][0] = r0; red[wid][1] = r1; red[wid][2] = r2; red[wid][3] = r3; }
    __syncthreads();

    if (j == 0) {
        float a0 = 0.f, a1 = 0.f, a2 = 0.f, a3 = 0.f;
#pragma unroll
        for (int w = 0; w < 4; w++) {
            a0 += red[w][0]; a1 += red[w][1]; a2 += red[w][2]; a3 += red[w][3];
        }
        const float diff   = fabsf((float)plen - (float)len);
        const float factor = 1.0f + 0.5f * (plen < len ? 1.0f : 0.0f)
                                  + 0.3f * (plen <= 3 ? 1.0f : 0.0f);
        float* P = g_part + b * 6;
        P[0] = a0;            // sum(ce*bw)
        P[1] = a1;            // sum(bw)
        P[2] = a2;            // bigram partial
        P[3] = a3;            // trigram partial
        P[4] = diff * factor; // length-penalty term
        P[5] = (float)av;     // any_valid flag
    }
}

// ---------------------------------------------------------------------------
// Kernel 3: single-block deterministic final reduction.
// ---------------------------------------------------------------------------
__global__ void __launch_bounds__(512) k_final(float* __restrict__ out)
{
    const int i = threadIdx.x;
    __shared__ float sh[512][6];
#pragma unroll
    for (int k = 0; k < 6; k++) sh[i][k] = g_part[i * 6 + k];
    __syncthreads();

    for (int off = 256; off; off >>= 1) {
        if (i < off) {
#pragma unroll
            for (int k = 0; k < 6; k++) sh[i][k] += sh[i + off][k];
        }
        __syncthreads();
    }

    if (i == 0) {
        const float weighted = sh[0][0] / sh[0][1];
        const float bigram   = sh[0][2] / (float)(BB * (SS - 1) * VV);
        const float trigram  = sh[0][3] / (float)(BB * (SS - 2) * VV);
        const float lenpen   = 0.3f * (sh[0][4] / (float)BB);
        const float ngram    = bigram + ((sh[0][5] > 0.f) ? 1.5f * trigram : 0.f);
        // DIFF_MULT=1, CHAR_W=0.2
        out[0] = weighted * 0.7f + lenpen * 0.2f + 0.2f * ngram * 0.1f;
    }
}

// ---------------------------------------------------------------------------
extern "C" void kernel_launch(void* const* d_in, const int* in_sizes, int n_in,
                              void* d_out, int out_size)
{
    const float* logits = nullptr;
    const int*   tgt    = nullptr;
    for (int i = 0; i < n_in; i++) {
        if (in_sizes[i] == BB * SS * VV)      logits = (const float*)d_in[i];
        else if (in_sizes[i] == BB * SS)      tgt    = (const int*)d_in[i];
    }
    k_row  <<<ROWS, 256>>>(logits, tgt);
    k_batch<<<BB,   128>>>(tgt);
    k_final<<<1,    512>>>((float*)d_out);
}

// round 2
// speedup vs baseline: 1.7732x; 1.7732x over previous
#include <cuda_runtime.h>

#define BB 512
#define SS 128
#define VV 2048
#define ROWS (BB*SS)

// Scratch (allocation-free: device globals)
__device__ float g_ce[ROWS];
__device__ int   g_pred[ROWS];
__device__ float g_part[BB * 6];

__device__ __forceinline__ float pick4(float4 q, int k) {
    return (k == 0) ? q.x : (k == 1) ? q.y : (k == 2) ? q.z : q.w;
}

// ---------------------------------------------------------------------------
// Kernel 1: ONE WARP per (b,s) row of 2048 logits. No barriers, no smem.
// Each lane holds 16 float4 = 64 values in registers; warp butterfly reductions.
// ---------------------------------------------------------------------------
__global__ void __launch_bounds__(256) k_row(const float4* __restrict__ logits,
                                             const int*    __restrict__ tgt)
{
    const int row  = blockIdx.x * 8 + (threadIdx.x >> 5);
    const int lane = threadIdx.x & 31;
    const float4* base = logits + (size_t)row * (VV / 4);

    // Coalesced streaming load: 16 outstanding LDG.128 per lane.
    float4 q[16];
#pragma unroll
    for (int i = 0; i < 16; i++) q[i] = __ldcs(base + lane + 32 * i);

    const int t     = __ldg(tgt + row);
    const int f4    = t >> 2;
    const int owner = f4 & 31;
    const int qidx  = f4 >> 5;
    const int comp  = t & 3;

    // Pass 1: max+argmax (first-occurrence), sum, target pick (static indices).
    float mx = -3.402823466e+38f;
    int   mi = 0;
    float sx = 0.f;
    float xt = 0.f;
#pragma unroll
    for (int i = 0; i < 16; i++) {
        float vv[4] = {q[i].x, q[i].y, q[i].z, q[i].w};
#pragma unroll
        for (int k = 0; k < 4; k++) {
            const int gi = (lane + 32 * i) * 4 + k;   // increasing per lane
            if (vv[k] > mx) { mx = vv[k]; mi = gi; }  // strict > => earliest idx
            sx += vv[k];
        }
        if (owner == lane && qidx == i) xt = pick4(q[i], comp);
    }
    xt = __shfl_sync(0xFFFFFFFFu, xt, owner);

    // Butterfly reduce (max,idx) and sum — all lanes converge to same result.
#pragma unroll
    for (int off = 16; off; off >>= 1) {
        const float om = __shfl_xor_sync(0xFFFFFFFFu, mx, off);
        const int   oi = __shfl_xor_sync(0xFFFFFFFFu, mi, off);
        if (om > mx || (om == mx && oi < mi)) { mx = om; mi = oi; }
        sx += __shfl_xor_sync(0xFFFFFFFFu, sx, off);
    }

    // Pass 2: sum of exp(v - mx), 4-way ILP accumulators.
    float e0 = 0.f, e1 = 0.f, e2 = 0.f, e3 = 0.f;
#pragma unroll
    for (int i = 0; i < 16; i++) {
        e0 += __expf(q[i].x - mx);
        e1 += __expf(q[i].y - mx);
        e2 += __expf(q[i].z - mx);
        e3 += __expf(q[i].w - mx);
    }
    float se = (e0 + e1) + (e2 + e3);
#pragma unroll
    for (int off = 16; off; off >>= 1)
        se += __shfl_xor_sync(0xFFFFFFFFu, se, off);

    if (lane == 0) {
        const float lse = mx + logf(se);
        float cev = 0.f;
        if (t != 0) {  // PAD == 0
            const float nll = lse - xt;
            const float smo = lse - sx * (1.0f / (float)VV);
            cev = 0.9f * nll + 0.1f * smo;   // (1-LS)*nll + LS*(-mean logp)
        }
        g_ce[row]   = cev;
        g_pred[row] = mi;
    }
}

// ---------------------------------------------------------------------------
// Kernel 2: one block per batch row (128 threads = S positions).
// Position weights, length penalty, analytic n-gram counts; per-batch partials.
// ---------------------------------------------------------------------------
__global__ void __launch_bounds__(128) k_batch(const int* __restrict__ tgt)
{
    const int b = blockIdx.x, j = threadIdx.x;
    __shared__ int s_t[SS];
    __shared__ int s_p[SS];

    const int t = tgt[b * SS + j];
    const int p = g_pred[b * SS + j];
    const float c = g_ce[b * SS + j];
    s_t[j] = t; s_p[j] = p;

    const int len  = __syncthreads_count(t != 0);
    const int plen = __syncthreads_count(p != 0);
    const int av   = __syncthreads_or((j < SS - 2) && (t != 0));

    // position weight: exact replication of the sequential jnp.where chain
    float bw = 1.0f;
    if (j < len) {
        const int L = len;
        float w = 1.0f + ((float)j / (float)L) * 0.5f;
        if (j == L - 1)            w = 4.5f;   // END_W * 1.5
        if (L >= 2 && j == L - 2)  w = 3.0f;   // END_W * 1.0
        if (L >= 3 && j == L - 3)  w = 2.4f;   // END_W * 0.8
        if (L >= 4 && j >= L / 3 && j < (2 * L) / 3) w *= 1.3f;
        if (L <= 4)                w *= 1.2f;
        bw = w;
    }
    const float cw = c * bw;

    float big = 0.f, tri = 0.f;
    if (j < SS - 1) {
        const bool pb = (s_p[j] == s_p[j + 1]);
        const bool tb = (s_t[j] == s_t[j + 1]);
        const bool mb = pb && tb && (s_p[j] == s_t[j]);
        const float wq = (j >= SS - 3) ? 2.25f : 1.0f;           // 1.5^2
        big = ((float)pb + (float)tb - 2.0f * (float)mb) * wq;
    }
    if (j < SS - 2) {
        const bool pb0 = (s_p[j] == s_p[j + 1]), pb1 = (s_p[j + 1] == s_p[j + 2]);
        const bool tb0 = (s_t[j] == s_t[j + 1]), tb1 = (s_t[j + 1] == s_t[j + 2]);
        const bool pt = pb0 && pb1, tt = tb0 && tb1;
        const bool mt = pt && tt && (s_p[j] == s_t[j]);
        const float wq = (j >= SS - 4) ? 4.0f : 1.0f;            // 2.0^2
        tri = ((float)pt + (float)tt - 2.0f * (float)mt) * wq;
    }

    // block reduce 4 floats (deterministic)
    float r0 = cw, r1 = bw, r2 = big, r3 = tri;
#pragma unroll
    for (int off = 16; off; off >>= 1) {
        r0 += __shfl_down_sync(0xFFFFFFFFu, r0, off);
        r1 += __shfl_down_sync(0xFFFFFFFFu, r1, off);
        r2 += __shfl_down_sync(0xFFFFFFFFu, r2, off);
        r3 += __shfl_down_sync(0xFFFFFFFFu, r3, off);
    }
    __shared__ float red[4][4];
    const int wid = j >> 5, lane = j & 31;
    if (lane == 0) { red[wid][0] = r0; red[wid][1] = r1; red[wid][2] = r2; red[wid][3] = r3; }
    __syncthreads();

    if (j == 0) {
        float a0 = 0.f, a1 = 0.f, a2 = 0.f, a3 = 0.f;
#pragma unroll
        for (int w = 0; w < 4; w++) {
            a0 += red[w][0]; a1 += red[w][1]; a2 += red[w][2]; a3 += red[w][3];
        }
        const float diff   = fabsf((float)plen - (float)len);
        const float factor = 1.0f + 0.5f * (plen < len ? 1.0f : 0.0f)
                                  + 0.3f * (plen <= 3 ? 1.0f : 0.0f);
        float* P = g_part + b * 6;
        P[0] = a0;            // sum(ce*bw)
        P[1] = a1;            // sum(bw)
        P[2] = a2;            // bigram partial
        P[3] = a3;            // trigram partial
        P[4] = diff * factor; // length-penalty term
        P[5] = (float)av;     // any_valid flag
    }
}

// ---------------------------------------------------------------------------
// Kernel 3: single-block deterministic final reduction.
// ---------------------------------------------------------------------------
__global__ void __launch_bounds__(512) k_final(float* __restrict__ out)
{
    const int i = threadIdx.x;
    __shared__ float sh[512][6];
#pragma unroll
    for (int k = 0; k < 6; k++) sh[i][k] = g_part[i * 6 + k];
    __syncthreads();

    for (int off = 256; off; off >>= 1) {
        if (i < off) {
#pragma unroll
            for (int k = 0; k < 6; k++) sh[i][k] += sh[i + off][k];
        }
        __syncthreads();
    }

    if (i == 0) {
        const float weighted = sh[0][0] / sh[0][1];
        const float bigram   = sh[0][2] / (float)(BB * (SS - 1) * VV);
        const float trigram  = sh[0][3] / (float)(BB * (SS - 2) * VV);
        const float lenpen   = 0.3f * (sh[0][4] / (float)BB);
        const float ngram    = bigram + ((sh[0][5] > 0.f) ? 1.5f * trigram : 0.f);
        // DIFF_MULT=1, CHAR_W=0.2
        out[0] = weighted * 0.7f + lenpen * 0.2f + 0.2f * ngram * 0.1f;
    }
}

// ---------------------------------------------------------------------------
extern "C" void kernel_launch(void* const* d_in, const int* in_sizes, int n_in,
                              void* d_out, int out_size)
{
    const float* logits = nullptr;
    const int*   tgt    = nullptr;
    for (int i = 0; i < n_in; i++) {
        if (in_sizes[i] == BB * SS * VV)      logits = (const float*)d_in[i];
        else if (in_sizes[i] == BB * SS)      tgt    = (const int*)d_in[i];
    }
    k_row  <<<ROWS / 8, 256>>>((const float4*)logits, tgt);
    k_batch<<<BB,       128>>>(tgt);
    k_final<<<1,        512>>>((float*)d_out);
}

// round 4
// speedup vs baseline: 1.8229x; 1.0280x over previous
#include <cuda_runtime.h>

#define BB 512
#define SS 128
#define VV 2048
#define ROWS (BB*SS)

// Scratch (allocation-free: device globals)
__device__ float    g_ce[ROWS];
__device__ int      g_pred[ROWS];
__device__ float    g_part[BB * 6];
__device__ unsigned g_ctr = 0;

// ---------------------------------------------------------------------------
// Kernel 1: ONE WARP per (b,s) row of 2048 logits. No barriers, no smem.
// Group-level (float4) argmax to keep ALU pipe cold; lane-local exp + rescale.
// ---------------------------------------------------------------------------
__global__ void __launch_bounds__(256) k_row(const float4* __restrict__ logits,
                                             const int*    __restrict__ tgt)
{
    const int row  = blockIdx.x * 8 + (threadIdx.x >> 5);
    const int lane = threadIdx.x & 31;
    const float4* base = logits + (size_t)row * (VV / 4);

    // Prefetch target logit (lane 0 only) alongside the main streaming loads.
    const int t = __ldg(tgt + row);
    float xt = 0.f;
    if (lane == 0) xt = __ldg(((const float*)base) + t);

    // Coalesced streaming load: 16 outstanding LDG.128 per lane.
    float4 q[16];
#pragma unroll
    for (int i = 0; i < 16; i++) q[i] = __ldcs(base + lane + 32 * i);

    // Pass 1: group max (FMA pipe) + group-index argmax (1 cmp/sel) + sum.
    float mx = -3.402823466e+38f;
    int   gi = 0;                       // global float4-group index of max
    float sx = 0.f;
#pragma unroll
    for (int i = 0; i < 16; i++) {
        const float gm = fmaxf(fmaxf(q[i].x, q[i].y), fmaxf(q[i].z, q[i].w));
        if (gm > mx) { mx = gm; gi = lane + 32 * i; }  // strict > => earliest group
        sx += (q[i].x + q[i].y) + (q[i].z + q[i].w);
    }

    // Pass 2: exp referenced to LANE-LOCAL max (no cross-lane dependency).
    float e0 = 0.f, e1 = 0.f, e2 = 0.f, e3 = 0.f;
#pragma unroll
    for (int i = 0; i < 16; i++) {
        e0 += __expf(q[i].x - mx);
        e1 += __expf(q[i].y - mx);
        e2 += __expf(q[i].z - mx);
        e3 += __expf(q[i].w - mx);
    }
    float se = (e0 + e1) + (e2 + e3);
    const float mxl = mx;

    // Butterfly reduce (max, group-idx) with first-occurrence tie-break.
#pragma unroll
    for (int off = 16; off; off >>= 1) {
        const float om = __shfl_xor_sync(0xFFFFFFFFu, mx, off);
        const int   oi = __shfl_xor_sync(0xFFFFFFFFu, gi, off);
        if (om > mx || (om == mx && oi < gi)) { mx = om; gi = oi; }
    }

    // Rescale lane-local expsum to global max, then reduce se and sx.
    se *= __expf(mxl - mx);
#pragma unroll
    for (int off = 16; off; off >>= 1) {
        se += __shfl_xor_sync(0xFFFFFFFFu, se, off);
        sx += __shfl_xor_sync(0xFFFFFFFFu, sx, off);
    }

    if (lane == 0) {
        // Recover component within the winning group (bitwise-exact equality).
        const float4 g = __ldg(base + gi);
        const int comp = (g.x == mx) ? 0 : (g.y == mx) ? 1 : (g.z == mx) ? 2 : 3;
        g_pred[row] = gi * 4 + comp;

        const float lse = mx + logf(se);
        float cev = 0.f;
        if (t != 0) {  // PAD == 0
            const float nll = lse - xt;
            const float smo = lse - sx * (1.0f / (float)VV);
            cev = 0.9f * nll + 0.1f * smo;   // (1-LS)*nll + LS*(-mean logp)
        }
        g_ce[row] = cev;
    }
}

// ---------------------------------------------------------------------------
// Kernel 2: one block per batch row (128 threads = S positions), with the
// final reduction fused in via the last-block-done pattern (deterministic:
// fixed summation order independent of which block finishes last).
// ---------------------------------------------------------------------------
__global__ void __launch_bounds__(128) k_batch(const int* __restrict__ tgt,
                                               float* __restrict__ out)
{
    const int b = blockIdx.x, j = threadIdx.x;
    __shared__ int s_t[SS];
    __shared__ int s_p[SS];

    const int t = tgt[b * SS + j];
    const int p = g_pred[b * SS + j];
    const float c = g_ce[b * SS + j];
    s_t[j] = t; s_p[j] = p;

    const int len  = __syncthreads_count(t != 0);
    const int plen = __syncthreads_count(p != 0);
    const int av   = __syncthreads_or((j < SS - 2) && (t != 0));

    // position weight: exact replication of the sequential jnp.where chain
    float bw = 1.0f;
    if (j < len) {
        const int L = len;
        float w = 1.0f + ((float)j / (float)L) * 0.5f;
        if (j == L - 1)            w = 4.5f;   // END_W * 1.5
        if (L >= 2 && j == L - 2)  w = 3.0f;   // END_W * 1.0
        if (L >= 3 && j == L - 3)  w = 2.4f;   // END_W * 0.8
        if (L >= 4 && j >= L / 3 && j < (2 * L) / 3) w *= 1.3f;
        if (L <= 4)                w *= 1.2f;
        bw = w;
    }
    const float cw = c * bw;

    float big = 0.f, tri = 0.f;
    if (j < SS - 1) {
        const bool pb = (s_p[j] == s_p[j + 1]);
        const bool tb = (s_t[j] == s_t[j + 1]);
        const bool mb = pb && tb && (s_p[j] == s_t[j]);
        const float wq = (j >= SS - 3) ? 2.25f : 1.0f;           // 1.5^2
        big = ((float)pb + (float)tb - 2.0f * (float)mb) * wq;
    }
    if (j < SS - 2) {
        const bool pb0 = (s_p[j] == s_p[j + 1]), pb1 = (s_p[j + 1] == s_p[j + 2]);
        const bool tb0 = (s_t[j] == s_t[j + 1]), tb1 = (s_t[j + 1] == s_t[j + 2]);
        const bool pt = pb0 && pb1, tt = tb0 && tb1;
        const bool mt = pt && tt && (s_p[j] == s_t[j]);
        const float wq = (j >= SS - 4) ? 4.0f : 1.0f;            // 2.0^2
        tri = ((float)pt + (float)tt - 2.0f * (float)mt) * wq;
    }

    // block reduce 4 floats (deterministic)
    float r0 = cw, r1 = bw, r2 = big, r3 = tri;
#pragma unroll
    for (int off = 16; off; off >>= 1) {
        r0 += __shfl_down_sync(0xFFFFFFFFu, r0, off);
        r1 += __shfl_down_sync(0xFFFFFFFFu, r1, off);
        r2 += __shfl_down_sync(0xFFFFFFFFu, r2, off);
        r3 += __shfl_down_sync(0xFFFFFFFFu, r3, off);
    }
    __shared__ float red[4][4];
    const int wid = j >> 5, lane = j & 31;
    if (lane == 0) { red[wid][0] = r0; red[wid][1] = r1; red[wid][2] = r2; red[wid][3] = r3; }
    __syncthreads();

    if (j == 0) {
        float a0 = 0.f, a1 = 0.f, a2 = 0.f, a3 = 0.f;
#pragma unroll
        for (int w = 0; w < 4; w++) {
            a0 += red[w][0]; a1 += red[w][1]; a2 += red[w][2]; a3 += red[w][3];
        }
        const float diff   = fabsf((float)plen - (float)len);
        const float factor = 1.0f + 0.5f * (plen < len ? 1.0f : 0.0f)
                                  + 0.3f * (plen <= 3 ? 1.0f : 0.0f);
        float* P = g_part + b * 6;
        P[0] = a0;            // sum(ce*bw)
        P[1] = a1;            // sum(bw)
        P[2] = a2;            // bigram partial
        P[3] = a3;            // trigram partial
        P[4] = diff * factor; // length-penalty term
        P[5] = (float)av;     // any_valid flag
    }

    // ---- fused final reduction: last block to finish does the global sum ----
    __threadfence();
    __shared__ int s_last;
    if (j == 0) s_last = (atomicAdd(&g_ctr, 1u) == (unsigned)(BB - 1)) ? 1 : 0;
    __syncthreads();
    if (s_last) {
        float a[6] = {0.f, 0.f, 0.f, 0.f, 0.f, 0.f};
        for (int b2 = j; b2 < BB; b2 += 128) {
#pragma unroll
            for (int k = 0; k < 6; k++) a[k] += g_part[b2 * 6 + k];
        }
        __shared__ float sh[128][6];
#pragma unroll
        for (int k = 0; k < 6; k++) sh[j][k] = a[k];
        __syncthreads();
        for (int off = 64; off; off >>= 1) {
            if (j < off) {
#pragma unroll
                for (int k = 0; k < 6; k++) sh[j][k] += sh[j + off][k];
            }
            __syncthreads();
        }
        if (j == 0) {
            const float weighted = sh[0][0] / sh[0][1];
            const float bigram   = sh[0][2] / (float)((size_t)BB * (SS - 1) * VV);
            const float trigram  = sh[0][3] / (float)((size_t)BB * (SS - 2) * VV);
            const float lenpen   = 0.3f * (sh[0][4] / (float)BB);
            const float ngram    = bigram + ((sh[0][5] > 0.f) ? 1.5f * trigram : 0.f);
            // DIFF_MULT=1, CHAR_W=0.2
            out[0] = weighted * 0.7f + lenpen * 0.2f + 0.2f * ngram * 0.1f;
            g_ctr = 0;   // reset for next graph replay (deterministic)
        }
    }
}

// ---------------------------------------------------------------------------
extern "C" void kernel_launch(void* const* d_in, const int* in_sizes, int n_in,
                              void* d_out, int out_size)
{
    const float* logits = nullptr;
    const int*   tgt    = nullptr;
    for (int i = 0; i < n_in; i++) {
        if (in_sizes[i] == BB * SS * VV)      logits = (const float*)d_in[i];
        else if (in_sizes[i] == BB * SS)      tgt    = (const int*)d_in[i];
    }
    k_row  <<<ROWS / 8, 256>>>((const float4*)logits, tgt);
    k_batch<<<BB,       128>>>(tgt, (float*)d_out);
}

// round 7
// speedup vs baseline: 1.8485x; 1.0140x over previous
#include <cuda_runtime.h>

#define BB 512
#define SS 128
#define VV 2048
#define ROWS (BB*SS)

// Scratch (allocation-free: device globals)
__device__ float    g_ce[ROWS];
__device__ int      g_pred[ROWS];
__device__ float    g_part[BB * 6];
__device__ unsigned g_ctr = 0;

// ---------------------------------------------------------------------------
// Kernel 1: ONE WARP per (b,s) row of 2048 logits. No barriers, no smem.
// Group-level (float4) argmax to keep ALU pipe cold; lane-local exp + rescale.
// (Unchanged — measured at ~86% of HBM spec in R4.)
// ---------------------------------------------------------------------------
__global__ void __launch_bounds__(256) k_row(const float4* __restrict__ logits,
                                             const int*    __restrict__ tgt)
{
    const int row  = blockIdx.x * 8 + (threadIdx.x >> 5);
    const int lane = threadIdx.x & 31;
    const float4* base = logits + (size_t)row * (VV / 4);

    const int t = __ldg(tgt + row);
    float xt = 0.f;
    if (lane == 0) xt = __ldg(((const float*)base) + t);

    float4 q[16];
#pragma unroll
    for (int i = 0; i < 16; i++) q[i] = __ldcs(base + lane + 32 * i);

    float mx = -3.402823466e+38f;
    int   gi = 0;
    float sx = 0.f;
#pragma unroll
    for (int i = 0; i < 16; i++) {
        const float gm = fmaxf(fmaxf(q[i].x, q[i].y), fmaxf(q[i].z, q[i].w));
        if (gm > mx) { mx = gm; gi = lane + 32 * i; }  // strict > => earliest group
        sx += (q[i].x + q[i].y) + (q[i].z + q[i].w);
    }

    float e0 = 0.f, e1 = 0.f, e2 = 0.f, e3 = 0.f;
#pragma unroll
    for (int i = 0; i < 16; i++) {
        e0 += __expf(q[i].x - mx);
        e1 += __expf(q[i].y - mx);
        e2 += __expf(q[i].z - mx);
        e3 += __expf(q[i].w - mx);
    }
    float se = (e0 + e1) + (e2 + e3);
    const float mxl = mx;

#pragma unroll
    for (int off = 16; off; off >>= 1) {
        const float om = __shfl_xor_sync(0xFFFFFFFFu, mx, off);
        const int   oi = __shfl_xor_sync(0xFFFFFFFFu, gi, off);
        if (om > mx || (om == mx && oi < gi)) { mx = om; gi = oi; }
    }

    se *= __expf(mxl - mx);
#pragma unroll
    for (int off = 16; off; off >>= 1) {
        se += __shfl_xor_sync(0xFFFFFFFFu, se, off);
        sx += __shfl_xor_sync(0xFFFFFFFFu, sx, off);
    }

    if (lane == 0) {
        const float4 g = __ldg(base + gi);
        const int comp = (g.x == mx) ? 0 : (g.y == mx) ? 1 : (g.z == mx) ? 2 : 3;
        g_pred[row] = gi * 4 + comp;

        const float lse = mx + logf(se);
        float cev = 0.f;
        if (t != 0) {  // PAD == 0
            const float nll = lse - xt;
            const float smo = lse - sx * (1.0f / (float)VV);
            cev = 0.9f * nll + 0.1f * smo;
        }
        g_ce[row] = cev;
    }
}

// ---------------------------------------------------------------------------
// Kernel 2: WARP-PER-BATCH (512 warps = 64 blocks x 8 warps). Each lane owns
// 4 consecutive positions (int4/float4 loads). No __syncthreads in main path.
// Final reduction fused via last-block-done pattern (deterministic order).
// ---------------------------------------------------------------------------
__global__ void __launch_bounds__(256) k_batch(const int* __restrict__ tgt,
                                               float* __restrict__ out)
{
    const int b    = blockIdx.x * 8 + (threadIdx.x >> 5);
    const int lane = threadIdx.x & 31;
    const int j0   = lane * 4;

    const int4   tv = __ldg((const int4*)  (tgt    + b * SS) + lane);
    const int4   pv = __ldg((const int4*)  (g_pred + b * SS) + lane);
    const float4 cv = __ldg((const float4*)(g_ce   + b * SS) + lane);
    const int   tA[4] = {tv.x, tv.y, tv.z, tv.w};
    const int   pA[4] = {pv.x, pv.y, pv.z, pv.w};
    const float cA[4] = {cv.x, cv.y, cv.z, cv.w};

    // Neighbor positions (first two of lane+1). Lane 31's values are unused
    // because j=126 (trigram) and j=127 (bigram) are excluded by j-bounds.
    const int nt0 = __shfl_down_sync(0xFFFFFFFFu, tA[0], 1);
    const int nt1 = __shfl_down_sync(0xFFFFFFFFu, tA[1], 1);
    const int np0 = __shfl_down_sync(0xFFFFFFFFu, pA[0], 1);
    const int np1 = __shfl_down_sync(0xFFFFFFFFu, pA[1], 1);
    const int t6[6] = {tA[0], tA[1], tA[2], tA[3], nt0, nt1};
    const int p6[6] = {pA[0], pA[1], pA[2], pA[3], np0, np1};

    // Warp-wide counts via REDUX (no barriers).
    int ct = 0, cp = 0;
#pragma unroll
    for (int k = 0; k < 4; k++) { ct += (tA[k] != 0); cp += (pA[k] != 0); }
    const int len  = __reduce_add_sync(0xFFFFFFFFu, ct);
    const int plen = __reduce_add_sync(0xFFFFFFFFu, cp);
    bool avl = false;
#pragma unroll
    for (int k = 0; k < 4; k++) avl |= (tA[k] != 0) && (j0 + k < SS - 2);
    const int av = __any_sync(0xFFFFFFFFu, avl) ? 1 : 0;

    float cw = 0.f, bwsum = 0.f, big = 0.f, tri = 0.f;
    const int L = len;
    const float invL = 0.5f / (float)(L > 0 ? L : 1);
#pragma unroll
    for (int k = 0; k < 4; k++) {
        const int j = j0 + k;
        // position weight: exact replication of the sequential jnp.where chain
        float bw = 1.0f;
        if (j < L) {
            float w = 1.0f + (float)j * invL;
            if (j == L - 1)            w = 4.5f;   // END_W * 1.5
            if (L >= 2 && j == L - 2)  w = 3.0f;   // END_W * 1.0
            if (L >= 3 && j == L - 3)  w = 2.4f;   // END_W * 0.8
            if (L >= 4 && j >= L / 3 && j < (2 * L) / 3) w *= 1.3f;
            if (L <= 4)                w *= 1.2f;
            bw = w;
        }
        cw    += cA[k] * bw;
        bwsum += bw;

        if (j < SS - 1) {
            const bool pb = (p6[k] == p6[k + 1]);
            const bool tb = (t6[k] == t6[k + 1]);
            const bool mb = pb && tb && (p6[k] == t6[k]);
            const float wq = (j >= SS - 3) ? 2.25f : 1.0f;       // 1.5^2
            big += ((float)pb + (float)tb - 2.0f * (float)mb) * wq;
        }
        if (j < SS - 2) {
            const bool pt = (p6[k] == p6[k + 1]) && (p6[k + 1] == p6[k + 2]);
            const bool tt = (t6[k] == t6[k + 1]) && (t6[k + 1] == t6[k + 2]);
            const bool mt = pt && tt && (p6[k] == t6[k]);
            const float wq = (j >= SS - 4) ? 4.0f : 1.0f;        // 2.0^2
            tri += ((float)pt + (float)tt - 2.0f * (float)mt) * wq;
        }
    }

    // Warp butterfly reduce 4 floats (deterministic).
#pragma unroll
    for (int off = 16; off; off >>= 1) {
        cw    += __shfl_xor_sync(0xFFFFFFFFu, cw,    off);
        bwsum += __shfl_xor_sync(0xFFFFFFFFu, bwsum, off);
        big   += __shfl_xor_sync(0xFFFFFFFFu, big,   off);
        tri   += __shfl_xor_sync(0xFFFFFFFFu, tri,   off);
    }

    if (lane == 0) {
        const float diff   = fabsf((float)plen - (float)len);
        const float factor = 1.0f + 0.5f * (plen < len ? 1.0f : 0.0f)
                                  + 0.3f * (plen <= 3 ? 1.0f : 0.0f);
        float* P = g_part + b * 6;
        P[0] = cw;
        P[1] = bwsum;
        P[2] = big;
        P[3] = tri;
        P[4] = diff * factor;
        P[5] = (float)av;
        __threadfence();
    }

    // ---- fused final reduction: last block to finish does the global sum ----
    const int j = threadIdx.x;
    __shared__ int s_last;
    __syncthreads();   // all 8 warps' g_part writes + fences done
    if (j == 0) s_last = (atomicAdd(&g_ctr, 1u) == 63u) ? 1 : 0;
    __syncthreads();
    if (s_last) {
        float a[6] = {0.f, 0.f, 0.f, 0.f, 0.f, 0.f};
        for (int b2 = j; b2 < BB; b2 += 256) {        // fixed order => deterministic
#pragma unroll
            for (int k = 0; k < 6; k++) a[k] += g_part[b2 * 6 + k];
        }
        __shared__ float sh[256][6];
#pragma unroll
        for (int k = 0; k < 6; k++) sh[j][k] = a[k];
        __syncthreads();
        for (int off = 128; off; off >>= 1) {
            if (j < off) {
#pragma unroll
                for (int k = 0; k < 6; k++) sh[j][k] += sh[j + off][k];
            }
            __syncthreads();
        }
        if (j == 0) {
            const float weighted = sh[0][0] / sh[0][1];
            const float bigram   = sh[0][2] / (float)((size_t)BB * (SS - 1) * VV);
            const float trigram  = sh[0][3] / (float)((size_t)BB * (SS - 2) * VV);
            const float lenpen   = 0.3f * (sh[0][4] / (float)BB);
            const float ngram    = bigram + ((sh[0][5] > 0.f) ? 1.5f * trigram : 0.f);
            // DIFF_MULT=1, CHAR_W=0.2
            out[0] = weighted * 0.7f + lenpen * 0.2f + 0.2f * ngram * 0.1f;
            g_ctr = 0;   // reset for next graph replay
        }
    }
}

// ---------------------------------------------------------------------------
extern "C" void kernel_launch(void* const* d_in, const int* in_sizes, int n_in,
                              void* d_out, int out_size)
{
    const float* logits = nullptr;
    const int*   tgt    = nullptr;
    for (int i = 0; i < n_in; i++) {
        if (in_sizes[i] == BB * SS * VV)      logits = (const float*)d_in[i];
        else if (in_sizes[i] == BB * SS)      tgt    = (const int*)d_in[i];
    }
    k_row  <<<ROWS / 8, 256>>>((const float4*)logits, tgt);
    k_batch<<<BB / 8,   256>>>(tgt, (float*)d_out);
}